// round 9
// baseline (speedup 1.0000x reference)
#include <cuda_runtime.h>
#include <cuda_bf16.h>
#include <math.h>

// Problem dims (fixed by the reference)
#define B_SZ 1024
#define D_SZ 2048
#define N_SZ 30000

// GEMM tiling
#define BM 128
#define BN 128
#define BK 16
#define TM 8
#define TN 8
// threads per block = (BM/TM)*(BN/TN) = 16*16 = 256

// Scratch for the memory-bank update argmax.
// -2 = row untouched, -1 = touched but no update_flag, >=0 = last updating step index.
__device__ int g_winner[N_SZ];

// ---------------------------------------------------------------------------
// Kernel 1: init winner array
// ---------------------------------------------------------------------------
__global__ void init_winner_kernel() {
    int i = blockIdx.x * blockDim.x + threadIdx.x;
    if (i < N_SZ) g_winner[i] = -2;
}

// ---------------------------------------------------------------------------
// Kernel 2: mark touched rows / find last updating step per row.
// NOTE: indexes is int32 (JAX x64 is disabled; jnp.int64 request silently
// downcasts to int32). atomicMax is commutative -> deterministic.
// ---------------------------------------------------------------------------
__global__ void mark_kernel(const int* __restrict__ indexes,
                            const int* __restrict__ update_flag) {
    int i = blockIdx.x * blockDim.x + threadIdx.x;
    if (i < B_SZ) {
        int y = indexes[i];
        int v = (update_flag[i] > 0) ? i : -1;
        if (y >= 0 && y < N_SZ) atomicMax(&g_winner[y], v);
    }
}

// ---------------------------------------------------------------------------
// Kernel 3: produce new_features. One block (256 threads) per row.
//   winner == -2 : copy original row
//   winner == -1 : normalize original row
//   winner >=  0 : normalize inputs[winner]
// ---------------------------------------------------------------------------
__global__ void update_rows_kernel(const float* __restrict__ inputs,
                                   const float* __restrict__ feats,
                                   float* __restrict__ out_feats) {
    int y = blockIdx.x;
    int t = threadIdx.x;            // 0..255, each handles 8 floats (2 x float4)
    int w = g_winner[y];

    const float* src = (w >= 0) ? (inputs + (size_t)w * D_SZ)
                                : (feats  + (size_t)y * D_SZ);
    float* dst = out_feats + (size_t)y * D_SZ;

    float4 v0 = *reinterpret_cast<const float4*>(src + t * 4);
    float4 v1 = *reinterpret_cast<const float4*>(src + 1024 + t * 4);

    if (w == -2) {  // untouched: plain copy (uniform branch across block)
        *reinterpret_cast<float4*>(dst + t * 4)        = v0;
        *reinterpret_cast<float4*>(dst + 1024 + t * 4) = v1;
        return;
    }

    float ss = v0.x * v0.x + v0.y * v0.y + v0.z * v0.z + v0.w * v0.w
             + v1.x * v1.x + v1.y * v1.y + v1.z * v1.z + v1.w * v1.w;

    // block reduction: warp shuffle then cross-warp via smem
    #pragma unroll
    for (int o = 16; o > 0; o >>= 1)
        ss += __shfl_xor_sync(0xffffffffu, ss, o);

    __shared__ float sred[8];
    __shared__ float stot;
    if ((t & 31) == 0) sred[t >> 5] = ss;
    __syncthreads();
    if (t < 8) {
        float v = sred[t];
        v += __shfl_xor_sync(0x000000ffu, v, 4);
        v += __shfl_xor_sync(0x000000ffu, v, 2);
        v += __shfl_xor_sync(0x000000ffu, v, 1);
        if (t == 0) stot = v;
    }
    __syncthreads();

    float inv = 1.0f / fmaxf(sqrtf(stot), 1e-12f);

    v0.x *= inv; v0.y *= inv; v0.z *= inv; v0.w *= inv;
    v1.x *= inv; v1.y *= inv; v1.z *= inv; v1.w *= inv;
    *reinterpret_cast<float4*>(dst + t * 4)        = v0;
    *reinterpret_cast<float4*>(dst + 1024 + t * 4) = v1;
}

// ---------------------------------------------------------------------------
// Kernel 4: SGEMM  C[b][n] = sum_k A[b][k] * F[n][k]
// A: [B_SZ, D_SZ] row-major, F: [N_SZ, D_SZ] row-major (so this is A @ F^T).
// 128x128 tile, BK=16, 256 threads, 8x8 accumulators per thread.
// ---------------------------------------------------------------------------
__global__ __launch_bounds__(256, 2)
void sgemm_kernel(const float* __restrict__ A,
                  const float* __restrict__ F,
                  float* __restrict__ C) {
    __shared__ __align__(16) float As[BK][BM];
    __shared__ __align__(16) float Bs[BK][BN];

    const int n0 = blockIdx.x * BN;   // column tile (over N)
    const int m0 = blockIdx.y * BM;   // row tile (over B)

    const int tid = threadIdx.x;
    const int tr  = tid >> 4;         // 0..15
    const int tc  = tid & 15;         // 0..15

    // cooperative load mapping: 128 rows x 4 float4 per row = 512 float4;
    // 256 threads -> 2 float4 each (row groups 0..63 and 64..127)
    const int lrow = tid >> 2;            // 0..63
    const int lcol = (tid & 3) << 2;      // 0,4,8,12 (float offset within BK)

    float acc[TM][TN];
    #pragma unroll
    for (int i = 0; i < TM; i++)
        #pragma unroll
        for (int j = 0; j < TN; j++)
            acc[i][j] = 0.0f;

    const float* Abase = A + (size_t)m0 * D_SZ;
    const float* Fbase = F + (size_t)n0 * D_SZ;

    for (int k0 = 0; k0 < D_SZ; k0 += BK) {
        // --- load A tile (B rows always in-bounds: B_SZ % BM == 0) ---
        #pragma unroll
        for (int s = 0; s < 2; s++) {
            int row = lrow + s * 64;
            float4 a = *reinterpret_cast<const float4*>(
                Abase + (size_t)row * D_SZ + k0 + lcol);
            As[lcol + 0][row] = a.x;
            As[lcol + 1][row] = a.y;
            As[lcol + 2][row] = a.z;
            As[lcol + 3][row] = a.w;
        }
        // --- load F tile (guard N edge) ---
        #pragma unroll
        for (int s = 0; s < 2; s++) {
            int row = lrow + s * 64;
            float4 b;
            if (n0 + row < N_SZ) {
                b = *reinterpret_cast<const float4*>(
                    Fbase + (size_t)row * D_SZ + k0 + lcol);
            } else {
                b = make_float4(0.f, 0.f, 0.f, 0.f);
            }
            Bs[lcol + 0][row] = b.x;
            Bs[lcol + 1][row] = b.y;
            Bs[lcol + 2][row] = b.z;
            Bs[lcol + 3][row] = b.w;
        }
        __syncthreads();

        #pragma unroll
        for (int k = 0; k < BK; k++) {
            float ra[TM], rb[TN];
            float4 a0 = *reinterpret_cast<const float4*>(&As[k][tr * TM]);
            float4 a1 = *reinterpret_cast<const float4*>(&As[k][tr * TM + 4]);
            float4 b0 = *reinterpret_cast<const float4*>(&Bs[k][tc * TN]);
            float4 b1 = *reinterpret_cast<const float4*>(&Bs[k][tc * TN + 4]);
            ra[0]=a0.x; ra[1]=a0.y; ra[2]=a0.z; ra[3]=a0.w;
            ra[4]=a1.x; ra[5]=a1.y; ra[6]=a1.z; ra[7]=a1.w;
            rb[0]=b0.x; rb[1]=b0.y; rb[2]=b0.z; rb[3]=b0.w;
            rb[4]=b1.x; rb[5]=b1.y; rb[6]=b1.z; rb[7]=b1.w;
            #pragma unroll
            for (int i = 0; i < TM; i++)
                #pragma unroll
                for (int j = 0; j < TN; j++)
                    acc[i][j] = fmaf(ra[i], rb[j], acc[i][j]);
        }
        __syncthreads();
    }

    // --- store (guard N edge; B edge never triggers) ---
    const int cbase = n0 + tc * TN;
    #pragma unroll
    for (int i = 0; i < TM; i++) {
        size_t m = (size_t)(m0 + tr * TM + i);
        float* Crow = C + m * (size_t)N_SZ + cbase;
        #pragma unroll
        for (int j = 0; j < TN; j++) {
            if (cbase + j < N_SZ) Crow[j] = acc[i][j];
        }
    }
}

// ---------------------------------------------------------------------------
// Launch. Inputs (metadata order): inputs f32[B,D], features f32[N,D],
// IoU f32[B] (unused by max_iou path), indexes int32[B] (JAX x64 disabled),
// update_flag int32[B].
// Output: concat( outputs f32[B,N], new_features f32[N,D] ).
// ---------------------------------------------------------------------------
extern "C" void kernel_launch(void* const* d_in, const int* in_sizes, int n_in,
                              void* d_out, int out_size) {
    const float* inputs      = (const float*)d_in[0];
    const float* features    = (const float*)d_in[1];
    // d_in[2] = IoU, unused (max_iou update ignores clamped IoU)
    const int*   indexes     = (const int*)d_in[3];   // int32, NOT int64
    const int*   update_flag = (const int*)d_in[4];

    float* out         = (float*)d_out;                    // [B, N]
    float* out_feats   = out + (size_t)B_SZ * N_SZ;        // [N, D]

    // GEMM (dominant cost) first
    dim3 ggrid((N_SZ + BN - 1) / BN, B_SZ / BM);
    sgemm_kernel<<<ggrid, 256>>>(inputs, features, out);

    // Memory-bank update pipeline
    init_winner_kernel<<<(N_SZ + 255) / 256, 256>>>();
    mark_kernel<<<(B_SZ + 255) / 256, 256>>>(indexes, update_flag);
    update_rows_kernel<<<N_SZ, 256>>>(inputs, features, out_feats);
}

// round 10
// speedup vs baseline: 1.0003x; 1.0003x over previous
#include <cuda_runtime.h>
#include <cuda_bf16.h>
#include <math.h>

// Problem dims (fixed by the reference)
#define B_SZ 1024
#define D_SZ 2048
#define N_SZ 30000

// GEMM tiling
#define BM 128
#define BN 128
#define BK 16
#define TM 8
#define TN 8
// threads per block = (BM/TM)*(BN/TN) = 16*16 = 256

// Scratch for the memory-bank update argmax.
// -2 = row untouched, -1 = touched but no update_flag, >=0 = last updating step index.
__device__ int g_winner[N_SZ];

// ---------------------------------------------------------------------------
// Kernel 1: init winner array
// ---------------------------------------------------------------------------
__global__ void init_winner_kernel() {
    int i = blockIdx.x * blockDim.x + threadIdx.x;
    if (i < N_SZ) g_winner[i] = -2;
}

// ---------------------------------------------------------------------------
// Kernel 2: mark touched rows / find last updating step per row.
// NOTE: indexes is int32 (JAX x64 is disabled; jnp.int64 request silently
// downcasts to int32). atomicMax is commutative -> deterministic.
// ---------------------------------------------------------------------------
__global__ void mark_kernel(const int* __restrict__ indexes,
                            const int* __restrict__ update_flag) {
    int i = blockIdx.x * blockDim.x + threadIdx.x;
    if (i < B_SZ) {
        int y = indexes[i];
        int v = (update_flag[i] > 0) ? i : -1;
        if (y >= 0 && y < N_SZ) atomicMax(&g_winner[y], v);
    }
}

// ---------------------------------------------------------------------------
// Kernel 3: produce new_features. One block (256 threads) per row.
//   winner == -2 : copy original row
//   winner == -1 : normalize original row
//   winner >=  0 : normalize inputs[winner]
// ---------------------------------------------------------------------------
__global__ void update_rows_kernel(const float* __restrict__ inputs,
                                   const float* __restrict__ feats,
                                   float* __restrict__ out_feats) {
    int y = blockIdx.x;
    int t = threadIdx.x;            // 0..255, each handles 8 floats (2 x float4)
    int w = g_winner[y];

    const float* src = (w >= 0) ? (inputs + (size_t)w * D_SZ)
                                : (feats  + (size_t)y * D_SZ);
    float* dst = out_feats + (size_t)y * D_SZ;

    float4 v0 = *reinterpret_cast<const float4*>(src + t * 4);
    float4 v1 = *reinterpret_cast<const float4*>(src + 1024 + t * 4);

    if (w == -2) {  // untouched: plain copy (uniform branch across block)
        *reinterpret_cast<float4*>(dst + t * 4)        = v0;
        *reinterpret_cast<float4*>(dst + 1024 + t * 4) = v1;
        return;
    }

    float ss = v0.x * v0.x + v0.y * v0.y + v0.z * v0.z + v0.w * v0.w
             + v1.x * v1.x + v1.y * v1.y + v1.z * v1.z + v1.w * v1.w;

    // block reduction: warp shuffle then cross-warp via smem
    #pragma unroll
    for (int o = 16; o > 0; o >>= 1)
        ss += __shfl_xor_sync(0xffffffffu, ss, o);

    __shared__ float sred[8];
    __shared__ float stot;
    if ((t & 31) == 0) sred[t >> 5] = ss;
    __syncthreads();
    if (t < 8) {
        float v = sred[t];
        v += __shfl_xor_sync(0x000000ffu, v, 4);
        v += __shfl_xor_sync(0x000000ffu, v, 2);
        v += __shfl_xor_sync(0x000000ffu, v, 1);
        if (t == 0) stot = v;
    }
    __syncthreads();

    float inv = 1.0f / fmaxf(sqrtf(stot), 1e-12f);

    v0.x *= inv; v0.y *= inv; v0.z *= inv; v0.w *= inv;
    v1.x *= inv; v1.y *= inv; v1.z *= inv; v1.w *= inv;
    *reinterpret_cast<float4*>(dst + t * 4)        = v0;
    *reinterpret_cast<float4*>(dst + 1024 + t * 4) = v1;
}

// ---------------------------------------------------------------------------
// Kernel 4: SGEMM  C[b][n] = sum_k A[b][k] * F[n][k]
// A: [B_SZ, D_SZ] row-major, F: [N_SZ, D_SZ] row-major (so this is A @ F^T).
// 128x128 tile, BK=16, 256 threads, 8x8 accumulators per thread.
// ---------------------------------------------------------------------------
__global__ __launch_bounds__(256, 2)
void sgemm_kernel(const float* __restrict__ A,
                  const float* __restrict__ F,
                  float* __restrict__ C) {
    __shared__ __align__(16) float As[BK][BM];
    __shared__ __align__(16) float Bs[BK][BN];

    const int n0 = blockIdx.x * BN;   // column tile (over N)
    const int m0 = blockIdx.y * BM;   // row tile (over B)

    const int tid = threadIdx.x;
    const int tr  = tid >> 4;         // 0..15
    const int tc  = tid & 15;         // 0..15

    // cooperative load mapping: 128 rows x 4 float4 per row = 512 float4;
    // 256 threads -> 2 float4 each (row groups 0..63 and 64..127)
    const int lrow = tid >> 2;            // 0..63
    const int lcol = (tid & 3) << 2;      // 0,4,8,12 (float offset within BK)

    float acc[TM][TN];
    #pragma unroll
    for (int i = 0; i < TM; i++)
        #pragma unroll
        for (int j = 0; j < TN; j++)
            acc[i][j] = 0.0f;

    const float* Abase = A + (size_t)m0 * D_SZ;
    const float* Fbase = F + (size_t)n0 * D_SZ;

    for (int k0 = 0; k0 < D_SZ; k0 += BK) {
        // --- load A tile (B rows always in-bounds: B_SZ % BM == 0) ---
        #pragma unroll
        for (int s = 0; s < 2; s++) {
            int row = lrow + s * 64;
            float4 a = *reinterpret_cast<const float4*>(
                Abase + (size_t)row * D_SZ + k0 + lcol);
            As[lcol + 0][row] = a.x;
            As[lcol + 1][row] = a.y;
            As[lcol + 2][row] = a.z;
            As[lcol + 3][row] = a.w;
        }
        // --- load F tile (guard N edge) ---
        #pragma unroll
        for (int s = 0; s < 2; s++) {
            int row = lrow + s * 64;
            float4 b;
            if (n0 + row < N_SZ) {
                b = *reinterpret_cast<const float4*>(
                    Fbase + (size_t)row * D_SZ + k0 + lcol);
            } else {
                b = make_float4(0.f, 0.f, 0.f, 0.f);
            }
            Bs[lcol + 0][row] = b.x;
            Bs[lcol + 1][row] = b.y;
            Bs[lcol + 2][row] = b.z;
            Bs[lcol + 3][row] = b.w;
        }
        __syncthreads();

        #pragma unroll
        for (int k = 0; k < BK; k++) {
            float ra[TM], rb[TN];
            float4 a0 = *reinterpret_cast<const float4*>(&As[k][tr * TM]);
            float4 a1 = *reinterpret_cast<const float4*>(&As[k][tr * TM + 4]);
            float4 b0 = *reinterpret_cast<const float4*>(&Bs[k][tc * TN]);
            float4 b1 = *reinterpret_cast<const float4*>(&Bs[k][tc * TN + 4]);
            ra[0]=a0.x; ra[1]=a0.y; ra[2]=a0.z; ra[3]=a0.w;
            ra[4]=a1.x; ra[5]=a1.y; ra[6]=a1.z; ra[7]=a1.w;
            rb[0]=b0.x; rb[1]=b0.y; rb[2]=b0.z; rb[3]=b0.w;
            rb[4]=b1.x; rb[5]=b1.y; rb[6]=b1.z; rb[7]=b1.w;
            #pragma unroll
            for (int i = 0; i < TM; i++)
                #pragma unroll
                for (int j = 0; j < TN; j++)
                    acc[i][j] = fmaf(ra[i], rb[j], acc[i][j]);
        }
        __syncthreads();
    }

    // --- store (guard N edge; B edge never triggers) ---
    const int cbase = n0 + tc * TN;
    #pragma unroll
    for (int i = 0; i < TM; i++) {
        size_t m = (size_t)(m0 + tr * TM + i);
        float* Crow = C + m * (size_t)N_SZ + cbase;
        #pragma unroll
        for (int j = 0; j < TN; j++) {
            if (cbase + j < N_SZ) Crow[j] = acc[i][j];
        }
    }
}

// ---------------------------------------------------------------------------
// Launch. Inputs (metadata order): inputs f32[B,D], features f32[N,D],
// IoU f32[B] (unused by max_iou path), indexes int32[B] (JAX x64 disabled),
// update_flag int32[B].
// Output: concat( outputs f32[B,N], new_features f32[N,D] ).
// ---------------------------------------------------------------------------
extern "C" void kernel_launch(void* const* d_in, const int* in_sizes, int n_in,
                              void* d_out, int out_size) {
    const float* inputs      = (const float*)d_in[0];
    const float* features    = (const float*)d_in[1];
    // d_in[2] = IoU, unused (max_iou update ignores clamped IoU)
    const int*   indexes     = (const int*)d_in[3];   // int32, NOT int64
    const int*   update_flag = (const int*)d_in[4];

    float* out         = (float*)d_out;                    // [B, N]
    float* out_feats   = out + (size_t)B_SZ * N_SZ;        // [N, D]

    // GEMM (dominant cost) first
    dim3 ggrid((N_SZ + BN - 1) / BN, B_SZ / BM);
    sgemm_kernel<<<ggrid, 256>>>(inputs, features, out);

    // Memory-bank update pipeline
    init_winner_kernel<<<(N_SZ + 255) / 256, 256>>>();
    mark_kernel<<<(B_SZ + 255) / 256, 256>>>(indexes, update_flag);
    update_rows_kernel<<<N_SZ, 256>>>(inputs, features, out_feats);
}